// round 1
// baseline (speedup 1.0000x reference)
#include <cuda_runtime.h>
#include <stdint.h>

// RT-DETR post-processing, GB300 sm_103a.
// Inputs (metadata order):
//   d_in[0]: pred_logits  float32 [256, 1000, 80]
//   d_in[1]: pred_boxes   float32 [256, 1000, 4]   (cx, cy, w, h)
//   d_in[2]: target_sizes float32 [256, 2]         (img_h, img_w)
// Output (float32, concatenated in reference tuple order):
//   [0      , 76800 ) out_scores [256, 300]
//   [76800  , 153600) out_labels [256, 300]  (int labels stored as float, -1 invalid)
//   [153600 , 460800) out_boxes  [256, 300, 4]
//
// Strategy: sigmoid is monotonic -> sort by raw max-logit; compute sigmoid only
// for the 300 survivors per row. Kernel 1 is the HBM-bound pass (82 MB logits),
// kernel 2 is a per-row bitonic top-k + epilogue.

#define NB   256          // batch
#define NQ   1000         // queries per batch
#define NC   80           // classes
#define TOPK 300
#define SORTN 1024        // next pow2 >= NQ

// prob > 0.05  <=>  logit > ln(0.05/0.95)
#define LOGIT_THRESH (-2.9444389791664403f)

// Scratch: 64-bit sort keys, one per (batch, query). 2 MB static device array
// (allocation-free per harness rules).
__device__ unsigned long long g_keys[NB * NQ];

// ---------------------------------------------------------------------------
// Kernel 1: per-query max/argmax over 80 classes, pack sort key.
// One warp per query. Lanes 0..19 each load one float4 (80 floats total,
// 320 contiguous bytes -> fully coalesced).
// ---------------------------------------------------------------------------
__global__ void __launch_bounds__(256) score_kernel(const float* __restrict__ logits) {
    int gwarp = (blockIdx.x * blockDim.x + threadIdx.x) >> 5;   // global query id
    int lane  = threadIdx.x & 31;
    if (gwarp >= NB * NQ) return;

    const float4* row = (const float4*)(logits + (size_t)gwarp * NC);

    float best = -INFINITY;
    int   bidx = 127;
    if (lane < NC / 4) {            // lanes 0..19
        float4 v = row[lane];
        int base = lane * 4;
        best = v.x; bidx = base;
        if (v.y > best) { best = v.y; bidx = base + 1; }
        if (v.z > best) { best = v.z; bidx = base + 2; }
        if (v.w > best) { best = v.w; bidx = base + 3; }
    }
    // Warp max/argmax reduction; ties -> lower class index (argmax semantics).
    #pragma unroll
    for (int off = 16; off; off >>= 1) {
        float ov = __shfl_down_sync(0xffffffffu, best, off);
        int   oi = __shfl_down_sync(0xffffffffu, bidx, off);
        if (ov > best || (ov == best && oi < bidx)) { best = ov; bidx = oi; }
    }

    if (lane == 0) {
        // Order-preserving float -> uint transform (handles negatives).
        unsigned u = __float_as_uint(best);
        u = (u & 0x80000000u) ? ~u : (u | 0x80000000u);
        int q_local = gwarp % NQ;
        // Low word: (1023 - q) in bits [8..17] so that for equal scores a lower
        // query index sorts first under DESCENDING sort; label in bits [0..7].
        unsigned lo = ((unsigned)(1023 - q_local) << 8) | (unsigned)bidx;
        g_keys[gwarp] = ((unsigned long long)u << 32) | lo;
    }
}

// ---------------------------------------------------------------------------
// Kernel 2: per-batch top-300 via bitonic sort of 1024 keys in smem + epilogue.
// One block (512 threads) per batch row.
// ---------------------------------------------------------------------------
__global__ void __launch_bounds__(512) topk_kernel(const float* __restrict__ boxes,
                                                   const float* __restrict__ tsz,
                                                   float* __restrict__ out) {
    __shared__ unsigned long long s[SORTN];
    int b   = blockIdx.x;
    int tid = threadIdx.x;

    for (int i = tid; i < SORTN; i += blockDim.x)
        s[i] = (i < NQ) ? g_keys[b * NQ + i] : 0ull;   // pad sorts last
    __syncthreads();

    // Bitonic sort, DESCENDING.
    for (int k = 2; k <= SORTN; k <<= 1) {
        for (int j = k >> 1; j > 0; j >>= 1) {
            for (int i = tid; i < SORTN; i += blockDim.x) {
                int ixj = i ^ j;
                if (ixj > i) {
                    unsigned long long a = s[i], c = s[ixj];
                    bool doswap = ((i & k) == 0) ? (a < c) : (a > c);
                    if (doswap) { s[i] = c; s[ixj] = a; }
                }
            }
            __syncthreads();
        }
    }

    if (tid < TOPK) {
        unsigned long long key = s[tid];
        unsigned u  = (unsigned)(key >> 32);
        // Invert the order-preserving transform.
        float logit = (u & 0x80000000u) ? __uint_as_float(u ^ 0x80000000u)
                                        : __uint_as_float(~u);
        float score = 1.0f / (1.0f + expf(-logit));
        bool  valid = (score > 0.05f);

        unsigned lo = (unsigned)(key & 0xffffffffu);
        int q     = 1023 - (int)((lo >> 8) & 0x3ffu);
        int label = (int)(lo & 0xffu);

        float4 bx = ((const float4*)boxes)[b * NQ + q];   // cx, cy, w, h
        float img_h = tsz[b * 2 + 0];
        float img_w = tsz[b * 2 + 1];
        float x0 = (bx.x - 0.5f * bx.z) * img_w;
        float y0 = (bx.y - 0.5f * bx.w) * img_h;
        float x1 = (bx.x + 0.5f * bx.z) * img_w;
        float y1 = (bx.y + 0.5f * bx.w) * img_h;

        float* out_scores = out;
        float* out_labels = out + NB * TOPK;
        float* out_boxes  = out + 2 * NB * TOPK;

        out_scores[b * TOPK + tid] = valid ? score : 0.0f;
        out_labels[b * TOPK + tid] = valid ? (float)label : -1.0f;
        float4 ob = valid ? make_float4(x0, y0, x1, y1)
                          : make_float4(0.f, 0.f, 0.f, 0.f);
        ((float4*)out_boxes)[b * TOPK + tid] = ob;
    }
}

// ---------------------------------------------------------------------------
extern "C" void kernel_launch(void* const* d_in, const int* in_sizes, int n_in,
                              void* d_out, int out_size) {
    const float* logits = (const float*)d_in[0];
    const float* boxes  = (const float*)d_in[1];
    const float* tsz    = (const float*)d_in[2];
    float* out = (float*)d_out;

    // 8 warps (= 8 queries) per block, 256000 queries total.
    score_kernel<<<(NB * NQ) / 8, 256>>>(logits);
    topk_kernel<<<NB, 512>>>(boxes, tsz, out);
}

// round 2
// speedup vs baseline: 1.6784x; 1.6784x over previous
#include <cuda_runtime.h>
#include <stdint.h>

// RT-DETR post-processing, GB300 sm_103a.
// d_in[0]: pred_logits  float32 [256, 1000, 80]
// d_in[1]: pred_boxes   float32 [256, 1000, 4]   (cx, cy, w, h)
// d_in[2]: target_sizes float32 [256, 2]         (img_h, img_w)
// Output float32 concat: [scores 256*300 | labels 256*300 | boxes 256*300*4]

#define NB   256
#define NQ   1000
#define NC   80
#define TOPK 300
#define SORTN 1024
#define QPW  8            // queries per warp in score kernel

__device__ unsigned long long g_keys[NB * NQ];

// ---------------------------------------------------------------------------
// Kernel 1: per-query max/argmax over 80 classes -> packed 64-bit sort key.
// Warp-per-query load layout (lanes 0..19 load one float4 each = 320 B
// contiguous, ~3 L1tex wavefronts), 8 queries per warp for MLP, REDUX-based
// argmax reduction (no shuffle chain).
// ---------------------------------------------------------------------------
__global__ void __launch_bounds__(256) score_kernel(const float* __restrict__ logits) {
    int warp_g = (blockIdx.x * blockDim.x + threadIdx.x) >> 5;
    int lane   = threadIdx.x & 31;
    int q0     = warp_g * QPW;
    bool act   = lane < (NC / 4);          // lanes 0..19

    const float4* base = (const float4*)logits;

    // Front-batched loads: 8 independent LDG.128 per lane.
    float4 v[QPW];
    #pragma unroll
    for (int s = 0; s < QPW; s++)
        if (act) v[s] = base[(size_t)(q0 + s) * (NC / 4) + lane];

    #pragma unroll
    for (int s = 0; s < QPW; s++) {
        unsigned u = 0;
        int bidx = 0;
        if (act) {
            float best = v[s].x; bidx = 0;
            if (v[s].y > best) { best = v[s].y; bidx = 1; }
            if (v[s].z > best) { best = v[s].z; bidx = 2; }
            if (v[s].w > best) { best = v[s].w; bidx = 3; }
            bidx += lane * 4;
            unsigned t = __float_as_uint(best);
            u = (t & 0x80000000u) ? ~t : (t | 0x80000000u);   // order-preserving
        }
        unsigned umax = __reduce_max_sync(0xffffffffu, u);
        unsigned ball = __ballot_sync(0xffffffffu, (u == umax) && act);
        int src  = __ffs(ball) - 1;              // lowest lane == lowest class group
        int label = __shfl_sync(0xffffffffu, bidx, src);
        if (lane == s) {                          // lanes 0..7 write the 8 keys
            int q = q0 + s;
            int q_local = q - (q / NQ) * NQ;
            unsigned lo = ((unsigned)(1023 - q_local) << 8) | (unsigned)label;
            g_keys[q] = ((unsigned long long)umax << 32) | lo;
        }
    }
}

// ---------------------------------------------------------------------------
// Hybrid bitonic helpers (descending sort).
// ---------------------------------------------------------------------------
__device__ __forceinline__ void shfl_merge(unsigned long long& v, unsigned i,
                                           unsigned k, int jstart) {
    #pragma unroll
    for (int j = 16; j >= 1; j >>= 1) {
        if (j <= jstart) {
            unsigned long long pv = __shfl_xor_sync(0xffffffffu, v, j);
            bool up    = ((i & k) == 0);          // descending block
            bool lower = ((i & (unsigned)j) == 0);
            bool keep_max = (up == lower);
            v = keep_max ? (v > pv ? v : pv) : (v < pv ? v : pv);
        }
    }
}

// ---------------------------------------------------------------------------
// Kernel 2: per-batch top-300 via hybrid (shfl + smem) bitonic sort of 1024
// keys, descending, then epilogue. One block (512 thr) per batch row.
// ---------------------------------------------------------------------------
__global__ void __launch_bounds__(512) topk_kernel(const float* __restrict__ boxes,
                                                   const float* __restrict__ tsz,
                                                   float* __restrict__ out) {
    __shared__ unsigned long long s[SORTN];
    int b   = blockIdx.x;
    int tid = threadIdx.x;

    s[tid]       = (tid       < NQ) ? g_keys[b * NQ + tid]       : 0ull;
    s[tid + 512] = (tid + 512 < NQ) ? g_keys[b * NQ + tid + 512] : 0ull;
    __syncthreads();

    // Phase A: k = 2..32 entirely in registers (15 shuffle stages, 0 barriers).
    {
        unsigned long long v0 = s[tid], v1 = s[tid + 512];
        unsigned i0 = tid, i1 = tid + 512;
        shfl_merge(v0, i0, 2, 1);   shfl_merge(v1, i1, 2, 1);
        shfl_merge(v0, i0, 4, 2);   shfl_merge(v1, i1, 4, 2);
        shfl_merge(v0, i0, 8, 4);   shfl_merge(v1, i1, 8, 4);
        shfl_merge(v0, i0, 16, 8);  shfl_merge(v1, i1, 16, 8);
        shfl_merge(v0, i0, 32, 16); shfl_merge(v1, i1, 32, 16);
        s[tid] = v0; s[tid + 512] = v1;
    }
    __syncthreads();

    // Phase B: k = 64..1024. j >= 32 via smem, j <= 16 via shuffles.
    for (unsigned k = 64; k <= SORTN; k <<= 1) {
        for (unsigned j = k >> 1; j >= 32; j >>= 1) {
            #pragma unroll
            for (int half = 0; half < 2; half++) {
                unsigned idx = tid + half * 512;
                unsigned ixj = idx ^ j;
                if (ixj > idx) {
                    unsigned long long a = s[idx], c = s[ixj];
                    bool doswap = ((idx & k) == 0) ? (a < c) : (a > c);
                    if (doswap) { s[idx] = c; s[ixj] = a; }
                }
            }
            __syncthreads();
        }
        unsigned long long v0 = s[tid], v1 = s[tid + 512];
        shfl_merge(v0, tid, k, 16);
        shfl_merge(v1, tid + 512, k, 16);
        s[tid] = v0; s[tid + 512] = v1;
        __syncthreads();
    }

    // Epilogue: threads 0..299 unpack, gather box, scale, write.
    if (tid < TOPK) {
        unsigned long long key = s[tid];
        unsigned u = (unsigned)(key >> 32);
        float logit = (u & 0x80000000u) ? __uint_as_float(u ^ 0x80000000u)
                                        : __uint_as_float(~u);
        float score = 1.0f / (1.0f + expf(-logit));
        bool  valid = (score > 0.05f);

        unsigned lo = (unsigned)(key & 0xffffffffu);
        int q     = 1023 - (int)((lo >> 8) & 0x3ffu);
        int label = (int)(lo & 0xffu);

        float4 bx = ((const float4*)boxes)[b * NQ + q];
        float img_h = tsz[b * 2 + 0];
        float img_w = tsz[b * 2 + 1];
        float x0 = (bx.x - 0.5f * bx.z) * img_w;
        float y0 = (bx.y - 0.5f * bx.w) * img_h;
        float x1 = (bx.x + 0.5f * bx.z) * img_w;
        float y1 = (bx.y + 0.5f * bx.w) * img_h;

        float* out_scores = out;
        float* out_labels = out + NB * TOPK;
        float* out_boxes  = out + 2 * NB * TOPK;

        out_scores[b * TOPK + tid] = valid ? score : 0.0f;
        out_labels[b * TOPK + tid] = valid ? (float)label : -1.0f;
        float4 ob = valid ? make_float4(x0, y0, x1, y1)
                          : make_float4(0.f, 0.f, 0.f, 0.f);
        ((float4*)out_boxes)[b * TOPK + tid] = ob;
    }
}

// ---------------------------------------------------------------------------
extern "C" void kernel_launch(void* const* d_in, const int* in_sizes, int n_in,
                              void* d_out, int out_size) {
    const float* logits = (const float*)d_in[0];
    const float* boxes  = (const float*)d_in[1];
    const float* tsz    = (const float*)d_in[2];
    float* out = (float*)d_out;

    // 8 warps/block, 8 queries/warp -> 64 queries/block.
    score_kernel<<<(NB * NQ) / (8 * QPW), 256>>>(logits);
    topk_kernel<<<NB, 512>>>(boxes, tsz, out);
}

// round 3
// speedup vs baseline: 1.8974x; 1.1305x over previous
#include <cuda_runtime.h>
#include <stdint.h>

// RT-DETR post-processing, GB300 sm_103a.
// d_in[0]: pred_logits  float32 [256, 1000, 80]
// d_in[1]: pred_boxes   float32 [256, 1000, 4]   (cx, cy, w, h)
// d_in[2]: target_sizes float32 [256, 2]         (img_h, img_w)
// Output float32 concat: [scores 256*300 | labels 256*300 | boxes 256*300*4]

#define NB   256
#define NQ   1000
#define NC   80
#define TOPK 300
#define QPW  8
#define CHUNK 512         // sort chunk size (2 chunks per row)

__device__ unsigned long long g_keys[NB * NQ];
__device__ unsigned long long g_sorted[NB * 2 * CHUNK];   // 2 MB

// ---------------------------------------------------------------------------
// Kernel 1: per-query max/argmax over 80 classes -> packed 64-bit sort key.
// ---------------------------------------------------------------------------
__global__ void __launch_bounds__(256) score_kernel(const float* __restrict__ logits) {
    int warp_g = (blockIdx.x * blockDim.x + threadIdx.x) >> 5;
    int lane   = threadIdx.x & 31;
    int q0     = warp_g * QPW;
    bool act   = lane < (NC / 4);          // lanes 0..19

    const float4* base = (const float4*)logits;

    float4 v[QPW];
    #pragma unroll
    for (int s = 0; s < QPW; s++)
        if (act) v[s] = base[(size_t)(q0 + s) * (NC / 4) + lane];

    #pragma unroll
    for (int s = 0; s < QPW; s++) {
        unsigned u = 0;
        int bidx = 0;
        if (act) {
            float best = v[s].x; bidx = 0;
            if (v[s].y > best) { best = v[s].y; bidx = 1; }
            if (v[s].z > best) { best = v[s].z; bidx = 2; }
            if (v[s].w > best) { best = v[s].w; bidx = 3; }
            bidx += lane * 4;
            unsigned t = __float_as_uint(best);
            u = (t & 0x80000000u) ? ~t : (t | 0x80000000u);   // order-preserving
        }
        unsigned umax = __reduce_max_sync(0xffffffffu, u);
        unsigned ball = __ballot_sync(0xffffffffu, (u == umax) && act);
        int src   = __ffs(ball) - 1;
        int label = __shfl_sync(0xffffffffu, bidx, src);
        if (lane == s) {
            int q = q0 + s;
            int q_local = q - (q / NQ) * NQ;
            unsigned lo = ((unsigned)(1023 - q_local) << 8) | (unsigned)label;
            g_keys[q] = ((unsigned long long)umax << 32) | lo;
        }
    }
}

// ---------------------------------------------------------------------------
// Bitonic shuffle merge for j <= 16 (descending within index space).
// ---------------------------------------------------------------------------
__device__ __forceinline__ void shfl_merge(unsigned long long& v, unsigned i,
                                           unsigned k) {
    #pragma unroll
    for (int j = 16; j >= 1; j >>= 1) {
        unsigned long long pv = __shfl_xor_sync(0xffffffffu, v, j);
        bool up    = ((i & k) == 0);
        bool lower = ((i & (unsigned)j) == 0);
        bool keep_max = (up == lower);
        v = keep_max ? (v > pv ? v : pv) : (v < pv ? v : pv);
    }
}
__device__ __forceinline__ void shfl_sort32(unsigned long long& v, unsigned i) {
    #pragma unroll
    for (unsigned k = 2; k <= 32; k <<= 1) {
        #pragma unroll
        for (int j = 16; j >= 1; j >>= 1) {
            if ((unsigned)j < k) {
                unsigned long long pv = __shfl_xor_sync(0xffffffffu, v, j);
                bool up    = ((i & k) == 0);
                bool lower = ((i & (unsigned)j) == 0);
                bool keep_max = (up == lower);
                v = keep_max ? (v > pv ? v : pv) : (v < pv ? v : pv);
            }
        }
    }
}

// ---------------------------------------------------------------------------
// Kernel 2: sort one 512-key chunk descending. grid = NB*2, block = 256.
// Chunk 1 of each row has 488 real keys + 24 zero pads (sort last).
// ---------------------------------------------------------------------------
__global__ void __launch_bounds__(256) chunk_sort_kernel() {
    __shared__ unsigned long long s[CHUNK];
    int b   = blockIdx.x >> 1;
    int c   = blockIdx.x & 1;
    int tid = threadIdx.x;

    int base = b * NQ + c * CHUNK;
    int nreal = c ? (NQ - CHUNK) : CHUNK;    // 488 or 512

    unsigned long long v0 = (tid         < nreal) ? g_keys[base + tid]       : 0ull;
    unsigned long long v1 = (tid + 256   < nreal) ? g_keys[base + tid + 256] : 0ull;
    unsigned i0 = (unsigned)tid, i1 = (unsigned)tid + 256;

    // Phase A: sort runs of 32 in registers (no barriers).
    shfl_sort32(v0, i0);
    shfl_sort32(v1, i1);
    s[i0] = v0; s[i1] = v1;
    __syncthreads();

    // Phase B: k = 64..512. j>=32 in smem, j<=16 via shuffles.
    #pragma unroll
    for (unsigned k = 64; k <= CHUNK; k <<= 1) {
        for (unsigned j = k >> 1; j >= 32; j >>= 1) {
            #pragma unroll
            for (int half = 0; half < 2; half++) {
                unsigned idx = (unsigned)tid + half * 256;
                unsigned ixj = idx ^ j;
                if (ixj > idx) {
                    unsigned long long a = s[idx], cc = s[ixj];
                    bool doswap = ((idx & k) == 0) ? (a < cc) : (a > cc);
                    if (doswap) { s[idx] = cc; s[ixj] = a; }
                }
            }
            __syncthreads();
        }
        v0 = s[i0]; v1 = s[i1];
        shfl_merge(v0, i0, k);
        shfl_merge(v1, i1, k);
        s[i0] = v0; s[i1] = v1;
        __syncthreads();
    }

    int obase = (b * 2 + c) * CHUNK;
    g_sorted[obase + i0] = s[i0];
    g_sorted[obase + i1] = s[i1];
}

// ---------------------------------------------------------------------------
// Kernel 3: merge-path select rank r (r<300) from two sorted-descending
// 512-lists, then epilogue. grid = NB, block = 512.
// Cross-list keys are strictly distinct (query id embedded; pads=0 never in
// top 300 since every real key > 0), so the merge is unambiguous.
// ---------------------------------------------------------------------------
__global__ void __launch_bounds__(512) merge_kernel(const float* __restrict__ boxes,
                                                    const float* __restrict__ tsz,
                                                    float* __restrict__ out) {
    __shared__ unsigned long long A[CHUNK];
    __shared__ unsigned long long B[CHUNK];
    int b   = blockIdx.x;
    int tid = threadIdx.x;

    A[tid] = g_sorted[(b * 2 + 0) * CHUNK + tid];
    B[tid] = g_sorted[(b * 2 + 1) * CHUNK + tid];
    __syncthreads();

    if (tid < TOPK) {
        int r = tid;
        // i* = number of A-elements among the top (r+1).
        int lo = 0, hi = r + 1;
        while (lo < hi) {
            int i = (lo + hi) >> 1;          // 0 <= i <= r < 512; 0 <= r-i < 512
            if (B[r - i] > A[i]) hi = i; else lo = i + 1;
        }
        int is = lo, js = r + 1 - lo;
        unsigned long long ka = is ? A[is - 1] : 0xFFFFFFFFFFFFFFFFull;
        unsigned long long kb = js ? B[js - 1] : 0xFFFFFFFFFFFFFFFFull;
        unsigned long long key = ka < kb ? ka : kb;

        unsigned u = (unsigned)(key >> 32);
        float logit = (u & 0x80000000u) ? __uint_as_float(u ^ 0x80000000u)
                                        : __uint_as_float(~u);
        float score = 1.0f / (1.0f + expf(-logit));
        bool  valid = (score > 0.05f);

        unsigned lw = (unsigned)(key & 0xffffffffu);
        int q     = 1023 - (int)((lw >> 8) & 0x3ffu);
        int label = (int)(lw & 0xffu);

        float4 bx = ((const float4*)boxes)[b * NQ + q];
        float img_h = tsz[b * 2 + 0];
        float img_w = tsz[b * 2 + 1];
        float x0 = (bx.x - 0.5f * bx.z) * img_w;
        float y0 = (bx.y - 0.5f * bx.w) * img_h;
        float x1 = (bx.x + 0.5f * bx.z) * img_w;
        float y1 = (bx.y + 0.5f * bx.w) * img_h;

        float* out_scores = out;
        float* out_labels = out + NB * TOPK;
        float* out_boxes  = out + 2 * NB * TOPK;

        out_scores[b * TOPK + r] = valid ? score : 0.0f;
        out_labels[b * TOPK + r] = valid ? (float)label : -1.0f;
        float4 ob = valid ? make_float4(x0, y0, x1, y1)
                          : make_float4(0.f, 0.f, 0.f, 0.f);
        ((float4*)out_boxes)[b * TOPK + r] = ob;
    }
}

// ---------------------------------------------------------------------------
extern "C" void kernel_launch(void* const* d_in, const int* in_sizes, int n_in,
                              void* d_out, int out_size) {
    const float* logits = (const float*)d_in[0];
    const float* boxes  = (const float*)d_in[1];
    const float* tsz    = (const float*)d_in[2];
    float* out = (float*)d_out;

    score_kernel<<<(NB * NQ) / (8 * QPW), 256>>>(logits);
    chunk_sort_kernel<<<NB * 2, 256>>>();
    merge_kernel<<<NB, 512>>>(boxes, tsz, out);
}

// round 4
// speedup vs baseline: 1.9221x; 1.0130x over previous
#include <cuda_runtime.h>
#include <stdint.h>

// RT-DETR post-processing, GB300 sm_103a.
// d_in[0]: pred_logits  float32 [256, 1000, 80]
// d_in[1]: pred_boxes   float32 [256, 1000, 4]   (cx, cy, w, h)
// d_in[2]: target_sizes float32 [256, 2]         (img_h, img_w)
// Output float32 concat: [scores 256*300 | labels 256*300 | boxes 256*300*4]

#define NB   256
#define NQ   1000
#define NC   80
#define TOPK 300
#define QPW  4            // queries per warp (v[] = 16 regs, no spill)
#define CHUNK 256         // sort chunk size (4 chunks per row)
#define NCHUNK 4

__device__ unsigned long long g_keys[NB * NQ];
__device__ unsigned long long g_sorted[NB * NCHUNK * CHUNK];   // 2 MB

// ---------------------------------------------------------------------------
// Kernel 1: per-query max/argmax over 80 classes -> packed 64-bit sort key.
// Warp-per-query loads (lanes 0..19, one float4 each = 320 B contiguous),
// QPW=4 front-batched LDG.128 with immediate offsets (no spills).
// ---------------------------------------------------------------------------
__global__ void __launch_bounds__(256) score_kernel(const float* __restrict__ logits) {
    int warp_g = (blockIdx.x * blockDim.x + threadIdx.x) >> 5;
    int lane   = threadIdx.x & 31;
    int q0     = warp_g * QPW;
    bool act   = lane < (NC / 4);          // lanes 0..19

    // Single address computation; p[s*20] -> LDG [R + s*320].
    const float4* p = (const float4*)logits + (size_t)q0 * (NC / 4) + lane;

    float4 v[QPW];
    #pragma unroll
    for (int s = 0; s < QPW; s++)
        if (act) v[s] = p[s * (NC / 4)];

    #pragma unroll
    for (int s = 0; s < QPW; s++) {
        unsigned u = 0;
        int bidx = 0;
        if (act) {
            float best = v[s].x; bidx = 0;
            if (v[s].y > best) { best = v[s].y; bidx = 1; }
            if (v[s].z > best) { best = v[s].z; bidx = 2; }
            if (v[s].w > best) { best = v[s].w; bidx = 3; }
            bidx += lane * 4;
            unsigned t = __float_as_uint(best);
            u = (t & 0x80000000u) ? ~t : (t | 0x80000000u);   // order-preserving
        }
        unsigned umax = __reduce_max_sync(0xffffffffu, u);
        unsigned ball = __ballot_sync(0xffffffffu, (u == umax) && act);
        int src   = __ffs(ball) - 1;             // lowest lane -> lowest class
        int label = __shfl_sync(0xffffffffu, bidx, src);
        if (lane == s) {                          // lanes 0..3 write the 4 keys
            int q = q0 + s;
            int q_local = q - (q / NQ) * NQ;
            unsigned lo = ((unsigned)(1023 - q_local) << 8) | (unsigned)label;
            g_keys[q] = ((unsigned long long)umax << 32) | lo;
        }
    }
}

// ---------------------------------------------------------------------------
// Bitonic helpers (descending).
// ---------------------------------------------------------------------------
__device__ __forceinline__ void shfl_merge(unsigned long long& v, unsigned i,
                                           unsigned k) {
    #pragma unroll
    for (int j = 16; j >= 1; j >>= 1) {
        unsigned long long pv = __shfl_xor_sync(0xffffffffu, v, j);
        bool up    = ((i & k) == 0);
        bool lower = ((i & (unsigned)j) == 0);
        bool keep_max = (up == lower);
        v = keep_max ? (v > pv ? v : pv) : (v < pv ? v : pv);
    }
}
__device__ __forceinline__ void shfl_sort32(unsigned long long& v, unsigned i) {
    #pragma unroll
    for (unsigned k = 2; k <= 32; k <<= 1) {
        #pragma unroll
        for (int j = 16; j >= 1; j >>= 1) {
            if ((unsigned)j < k) {
                unsigned long long pv = __shfl_xor_sync(0xffffffffu, v, j);
                bool up    = ((i & k) == 0);
                bool lower = ((i & (unsigned)j) == 0);
                bool keep_max = (up == lower);
                v = keep_max ? (v > pv ? v : pv) : (v < pv ? v : pv);
            }
        }
    }
}

// ---------------------------------------------------------------------------
// Kernel 2: sort one 256-key chunk descending. grid = NB*4, block = 128.
// Last chunk of each row has 232 real keys + zero pads (sort last).
// ---------------------------------------------------------------------------
__global__ void __launch_bounds__(128) chunk_sort_kernel() {
    __shared__ unsigned long long s[CHUNK];
    int b   = blockIdx.x >> 2;
    int c   = blockIdx.x & 3;
    int tid = threadIdx.x;

    int base  = b * NQ + c * CHUNK;
    int nreal = (c == 3) ? (NQ - 3 * CHUNK) : CHUNK;     // 232 or 256

    unsigned i0 = (unsigned)tid, i1 = (unsigned)tid + 128;
    unsigned long long v0 = ((int)i0 < nreal) ? g_keys[base + i0] : 0ull;
    unsigned long long v1 = ((int)i1 < nreal) ? g_keys[base + i1] : 0ull;

    shfl_sort32(v0, i0);
    shfl_sort32(v1, i1);
    s[i0] = v0; s[i1] = v1;
    __syncthreads();

    #pragma unroll
    for (unsigned k = 64; k <= CHUNK; k <<= 1) {
        for (unsigned j = k >> 1; j >= 32; j >>= 1) {
            #pragma unroll
            for (int half = 0; half < 2; half++) {
                unsigned idx = (unsigned)tid + half * 128;
                unsigned ixj = idx ^ j;
                if (ixj > idx) {
                    unsigned long long a = s[idx], cc = s[ixj];
                    bool doswap = ((idx & k) == 0) ? (a < cc) : (a > cc);
                    if (doswap) { s[idx] = cc; s[ixj] = a; }
                }
            }
            __syncthreads();
        }
        v0 = s[i0]; v1 = s[i1];
        shfl_merge(v0, i0, k);
        shfl_merge(v1, i1, k);
        s[i0] = v0; s[i1] = v1;
        __syncthreads();
    }

    int obase = (b * NCHUNK + c) * CHUNK;
    g_sorted[obase + i0] = s[i0];
    g_sorted[obase + i1] = s[i1];
}

// ---------------------------------------------------------------------------
// Merge-path rank select: key of rank r (descending) from two sorted lists.
// Keys are globally unique (query id embedded), so the merge is unambiguous.
// ---------------------------------------------------------------------------
__device__ __forceinline__ unsigned long long
rank_select(const unsigned long long* __restrict__ A,
            const unsigned long long* __restrict__ B,
            int r, int NA, int NBL) {
    int lo = r + 1 - NBL; if (lo < 0) lo = 0;
    int hi = r + 1;       if (hi > NA) hi = NA;
    while (lo < hi) {
        int i = (lo + hi) >> 1;
        if (B[r - i] > A[i]) hi = i; else lo = i + 1;
    }
    int is = lo, js = r + 1 - lo;
    unsigned long long ka = is ? A[is - 1] : 0xFFFFFFFFFFFFFFFFull;
    unsigned long long kb = js ? B[js - 1] : 0xFFFFFFFFFFFFFFFFull;
    return ka < kb ? ka : kb;
}

// ---------------------------------------------------------------------------
// Kernel 3: two-phase merge of 4 sorted 256-lists -> top-300, then epilogue.
// grid = NB, block = 512.
// ---------------------------------------------------------------------------
__global__ void __launch_bounds__(512) merge_kernel(const float* __restrict__ boxes,
                                                    const float* __restrict__ tsz,
                                                    float* __restrict__ out) {
    __shared__ unsigned long long L[NCHUNK * CHUNK];   // 4 sorted lists
    __shared__ unsigned long long M[2][TOPK];          // top-300 of AB, CD
    int b   = blockIdx.x;
    int tid = threadIdx.x;

    L[tid]       = g_sorted[b * NCHUNK * CHUNK + tid];
    L[tid + 512] = g_sorted[b * NCHUNK * CHUNK + tid + 512];
    __syncthreads();

    // Phase 1: top-300 of (list0 ∪ list1) and (list2 ∪ list3).
    for (int t = tid; t < 2 * TOPK; t += 512) {
        int pair = t / TOPK;            // 0 -> AB, 1 -> CD
        int r    = t - pair * TOPK;
        const unsigned long long* A = L + pair * 2 * CHUNK;
        const unsigned long long* B = A + CHUNK;
        M[pair][r] = rank_select(A, B, r, CHUNK, CHUNK);
    }
    __syncthreads();

    // Phase 2: rank r of M[0] ∪ M[1], then epilogue.
    if (tid < TOPK) {
        int r = tid;
        unsigned long long key = rank_select(M[0], M[1], r, TOPK, TOPK);

        unsigned u = (unsigned)(key >> 32);
        float logit = (u & 0x80000000u) ? __uint_as_float(u ^ 0x80000000u)
                                        : __uint_as_float(~u);
        float score = 1.0f / (1.0f + expf(-logit));
        bool  valid = (score > 0.05f);

        unsigned lw = (unsigned)(key & 0xffffffffu);
        int q     = 1023 - (int)((lw >> 8) & 0x3ffu);
        int label = (int)(lw & 0xffu);

        float4 bx = ((const float4*)boxes)[b * NQ + q];
        float img_h = tsz[b * 2 + 0];
        float img_w = tsz[b * 2 + 1];
        float x0 = (bx.x - 0.5f * bx.z) * img_w;
        float y0 = (bx.y - 0.5f * bx.w) * img_h;
        float x1 = (bx.x + 0.5f * bx.z) * img_w;
        float y1 = (bx.y + 0.5f * bx.w) * img_h;

        float* out_scores = out;
        float* out_labels = out + NB * TOPK;
        float* out_boxes  = out + 2 * NB * TOPK;

        out_scores[b * TOPK + r] = valid ? score : 0.0f;
        out_labels[b * TOPK + r] = valid ? (float)label : -1.0f;
        float4 ob = valid ? make_float4(x0, y0, x1, y1)
                          : make_float4(0.f, 0.f, 0.f, 0.f);
        ((float4*)out_boxes)[b * TOPK + r] = ob;
    }
}

// ---------------------------------------------------------------------------
extern "C" void kernel_launch(void* const* d_in, const int* in_sizes, int n_in,
                              void* d_out, int out_size) {
    const float* logits = (const float*)d_in[0];
    const float* boxes  = (const float*)d_in[1];
    const float* tsz    = (const float*)d_in[2];
    float* out = (float*)d_out;

    // 8 warps/block, 4 queries/warp -> 32 queries/block, 8000 blocks.
    score_kernel<<<(NB * NQ) / (8 * QPW), 256>>>(logits);
    chunk_sort_kernel<<<NB * NCHUNK, 128>>>();
    merge_kernel<<<NB, 512>>>(boxes, tsz, out);
}

// round 5
// speedup vs baseline: 2.0792x; 1.0817x over previous
#include <cuda_runtime.h>
#include <stdint.h>

// RT-DETR post-processing, GB300 sm_103a.
// d_in[0]: pred_logits  float32 [256, 1000, 80]
// d_in[1]: pred_boxes   float32 [256, 1000, 4]   (cx, cy, w, h)
// d_in[2]: target_sizes float32 [256, 2]         (img_h, img_w)
// Output float32 concat: [scores 256*300 | labels 256*300 | boxes 256*300*4]

#define NB   256
#define NQ   1000
#define NC   80
#define TOPK 300
#define QPW  4
#define CHUNK 256
#define NCHUNK 4

__device__ unsigned long long g_keys[NB * NQ];
__device__ unsigned long long g_sorted[NB * NCHUNK * CHUNK];   // 2 MB

// ---------------------------------------------------------------------------
// Kernel 1: per-query max/argmax over 80 classes -> packed 64-bit sort key.
// grid = (32, NB), block = 256 (8 warps x 4 queries).
// Lanes 20..31 duplicate lanes 0..11 (coalescer merges; no predication).
// Hot path per query: 3 FMNMX + 2-op transform + REDUX + ballot/FLO + shfl.
// ---------------------------------------------------------------------------
__global__ void __launch_bounds__(256) score_kernel(const float* __restrict__ logits) {
    int wid  = threadIdx.x >> 5;
    int lane = threadIdx.x & 31;
    int b    = blockIdx.y;
    int q0   = blockIdx.x * 32 + wid * QPW;       // query index within batch
    if (q0 >= NQ) return;                          // padded tail warps

    int lane20 = (lane < 20) ? lane : lane - 20;   // dup lanes -> same lines
    const float4* p = (const float4*)logits + ((size_t)b * NQ + q0) * (NC / 4) + lane20;

    float4 v[QPW];
    #pragma unroll
    for (int s = 0; s < QPW; s++) v[s] = p[s * (NC / 4)];   // 4 front-batched LDG.128

    #pragma unroll
    for (int s = 0; s < QPW; s++) {
        float m = fmaxf(fmaxf(v[s].x, v[s].y), fmaxf(v[s].z, v[s].w));
        unsigned t = __float_as_uint(m);
        unsigned u = t ^ ((unsigned)((int)t >> 31) | 0x80000000u);  // order-preserving
        unsigned umax = __reduce_max_sync(0xffffffffu, u);
        int src = __ffs(__ballot_sync(0xffffffffu, u == umax)) - 1; // lowest lane < 20
        int b4  = (v[s].x == m) ? 0 : (v[s].y == m) ? 1 : (v[s].z == m) ? 2 : 3;
        int label = src * 4 + __shfl_sync(0xffffffffu, b4, src);
        if (lane == s) {
            unsigned lo = ((unsigned)(1023 - (q0 + s)) << 8) | (unsigned)label;
            g_keys[b * NQ + q0 + s] = ((unsigned long long)umax << 32) | lo;
        }
    }
}

// ---------------------------------------------------------------------------
// Bitonic helpers (descending).
// ---------------------------------------------------------------------------
__device__ __forceinline__ void shfl_merge(unsigned long long& v, unsigned i,
                                           unsigned k) {
    #pragma unroll
    for (int j = 16; j >= 1; j >>= 1) {
        unsigned long long pv = __shfl_xor_sync(0xffffffffu, v, j);
        bool up    = ((i & k) == 0);
        bool lower = ((i & (unsigned)j) == 0);
        bool keep_max = (up == lower);
        v = keep_max ? (v > pv ? v : pv) : (v < pv ? v : pv);
    }
}
__device__ __forceinline__ void shfl_sort32(unsigned long long& v, unsigned i) {
    #pragma unroll
    for (unsigned k = 2; k <= 32; k <<= 1) {
        #pragma unroll
        for (int j = 16; j >= 1; j >>= 1) {
            if ((unsigned)j < k) {
                unsigned long long pv = __shfl_xor_sync(0xffffffffu, v, j);
                bool up    = ((i & k) == 0);
                bool lower = ((i & (unsigned)j) == 0);
                bool keep_max = (up == lower);
                v = keep_max ? (v > pv ? v : pv) : (v < pv ? v : pv);
            }
        }
    }
}

// ---------------------------------------------------------------------------
// Kernel 2: sort one 256-key chunk descending. grid = NB*4, block = 128.
// ---------------------------------------------------------------------------
__global__ void __launch_bounds__(128) chunk_sort_kernel() {
    __shared__ unsigned long long s[CHUNK];
    int b   = blockIdx.x >> 2;
    int c   = blockIdx.x & 3;
    int tid = threadIdx.x;

    int base  = b * NQ + c * CHUNK;
    int nreal = (c == 3) ? (NQ - 3 * CHUNK) : CHUNK;     // 232 or 256

    unsigned i0 = (unsigned)tid, i1 = (unsigned)tid + 128;
    unsigned long long v0 = ((int)i0 < nreal) ? g_keys[base + i0] : 0ull;
    unsigned long long v1 = ((int)i1 < nreal) ? g_keys[base + i1] : 0ull;

    shfl_sort32(v0, i0);
    shfl_sort32(v1, i1);
    s[i0] = v0; s[i1] = v1;
    __syncthreads();

    #pragma unroll
    for (unsigned k = 64; k <= CHUNK; k <<= 1) {
        for (unsigned j = k >> 1; j >= 32; j >>= 1) {
            #pragma unroll
            for (int half = 0; half < 2; half++) {
                unsigned idx = (unsigned)tid + half * 128;
                unsigned ixj = idx ^ j;
                if (ixj > idx) {
                    unsigned long long a = s[idx], cc = s[ixj];
                    bool doswap = ((idx & k) == 0) ? (a < cc) : (a > cc);
                    if (doswap) { s[idx] = cc; s[ixj] = a; }
                }
            }
            __syncthreads();
        }
        v0 = s[i0]; v1 = s[i1];
        shfl_merge(v0, i0, k);
        shfl_merge(v1, i1, k);
        s[i0] = v0; s[i1] = v1;
        __syncthreads();
    }

    int obase = (b * NCHUNK + c) * CHUNK;
    g_sorted[obase + i0] = s[i0];
    g_sorted[obase + i1] = s[i1];
}

// ---------------------------------------------------------------------------
// Merge-path rank select (descending, keys globally unique).
// ---------------------------------------------------------------------------
__device__ __forceinline__ unsigned long long
rank_select(const unsigned long long* __restrict__ A,
            const unsigned long long* __restrict__ B,
            int r, int NA, int NBL) {
    int lo = r + 1 - NBL; if (lo < 0) lo = 0;
    int hi = r + 1;       if (hi > NA) hi = NA;
    while (lo < hi) {
        int i = (lo + hi) >> 1;
        if (B[r - i] > A[i]) hi = i; else lo = i + 1;
    }
    int is = lo, js = r + 1 - lo;
    unsigned long long ka = is ? A[is - 1] : 0xFFFFFFFFFFFFFFFFull;
    unsigned long long kb = js ? B[js - 1] : 0xFFFFFFFFFFFFFFFFull;
    return ka < kb ? ka : kb;
}

// ---------------------------------------------------------------------------
// Kernel 3: two-phase merge of 4 sorted 256-lists -> top-300 + epilogue.
// grid = NB, block = 512.
// ---------------------------------------------------------------------------
__global__ void __launch_bounds__(512) merge_kernel(const float* __restrict__ boxes,
                                                    const float* __restrict__ tsz,
                                                    float* __restrict__ out) {
    __shared__ unsigned long long L[NCHUNK * CHUNK];
    __shared__ unsigned long long M[2][TOPK];
    int b   = blockIdx.x;
    int tid = threadIdx.x;

    L[tid]       = g_sorted[b * NCHUNK * CHUNK + tid];
    L[tid + 512] = g_sorted[b * NCHUNK * CHUNK + tid + 512];
    __syncthreads();

    for (int t = tid; t < 2 * TOPK; t += 512) {
        int pair = t / TOPK;
        int r    = t - pair * TOPK;
        const unsigned long long* A = L + pair * 2 * CHUNK;
        const unsigned long long* B = A + CHUNK;
        M[pair][r] = rank_select(A, B, r, CHUNK, CHUNK);
    }
    __syncthreads();

    if (tid < TOPK) {
        int r = tid;
        unsigned long long key = rank_select(M[0], M[1], r, TOPK, TOPK);

        unsigned u = (unsigned)(key >> 32);
        float logit = (u & 0x80000000u) ? __uint_as_float(u ^ 0x80000000u)
                                        : __uint_as_float(~u);
        float score = 1.0f / (1.0f + expf(-logit));
        bool  valid = (score > 0.05f);

        unsigned lw = (unsigned)(key & 0xffffffffu);
        int q     = 1023 - (int)((lw >> 8) & 0x3ffu);
        int label = (int)(lw & 0xffu);

        float4 bx = ((const float4*)boxes)[b * NQ + q];
        float img_h = tsz[b * 2 + 0];
        float img_w = tsz[b * 2 + 1];
        float x0 = (bx.x - 0.5f * bx.z) * img_w;
        float y0 = (bx.y - 0.5f * bx.w) * img_h;
        float x1 = (bx.x + 0.5f * bx.z) * img_w;
        float y1 = (bx.y + 0.5f * bx.w) * img_h;

        float* out_scores = out;
        float* out_labels = out + NB * TOPK;
        float* out_boxes  = out + 2 * NB * TOPK;

        out_scores[b * TOPK + r] = valid ? score : 0.0f;
        out_labels[b * TOPK + r] = valid ? (float)label : -1.0f;
        float4 ob = valid ? make_float4(x0, y0, x1, y1)
                          : make_float4(0.f, 0.f, 0.f, 0.f);
        ((float4*)out_boxes)[b * TOPK + r] = ob;
    }
}

// ---------------------------------------------------------------------------
extern "C" void kernel_launch(void* const* d_in, const int* in_sizes, int n_in,
                              void* d_out, int out_size) {
    const float* logits = (const float*)d_in[0];
    const float* boxes  = (const float*)d_in[1];
    const float* tsz    = (const float*)d_in[2];
    float* out = (float*)d_out;

    dim3 sgrid(32, NB);          // 32 blocks x 32 queries = 1024 >= 1000
    score_kernel<<<sgrid, 256>>>(logits);
    chunk_sort_kernel<<<NB * NCHUNK, 128>>>();
    merge_kernel<<<NB, 512>>>(boxes, tsz, out);
}

// round 6
// speedup vs baseline: 2.1794x; 1.0482x over previous
#include <cuda_runtime.h>
#include <stdint.h>

// RT-DETR post-processing, GB300 sm_103a.
// d_in[0]: pred_logits  float32 [256, 1000, 80]
// d_in[1]: pred_boxes   float32 [256, 1000, 4]   (cx, cy, w, h)
// d_in[2]: target_sizes float32 [256, 2]         (img_h, img_w)
// Output float32 concat: [scores 256*300 | labels 256*300 | boxes 256*300*4]

#define NB   256
#define NQ   1000
#define NC   80
#define TOPK 300
#define CHUNK 256

__device__ unsigned long long g_keys[NB * NQ];

// ---------------------------------------------------------------------------
// Kernel 1: 8 queries per warp. 5 coalesced LDG.128 (2560 B/warp) -> smem ->
// group-of-4-lanes per query. Every warp-instruction advances 8 queries.
// Lane 4g+j owns f4 chunks {g*20 + j + 4i}, i=0..4  (classes 4j+16i+e).
// Conflict-free: quad ids (4g+j+4i) mod 8 permute within each 8-lane subgroup.
// ---------------------------------------------------------------------------
__global__ void __launch_bounds__(256) score_kernel(const float* __restrict__ logits) {
    __shared__ float4 sh[8][160];          // 8 warps x 8 queries x 20 f4
    int wid  = threadIdx.x >> 5;
    int lane = threadIdx.x & 31;
    int b    = blockIdx.y;
    int q0   = blockIdx.x * 64 + wid * 8;
    if (q0 >= NQ) return;                  // tail warps in last block

    const float4* p = (const float4*)logits + ((size_t)b * NQ + q0) * 20 + lane;
    float4 a0 = p[0], a1 = p[32], a2 = p[64], a3 = p[96], a4 = p[128];
    sh[wid][lane      ] = a0;
    sh[wid][lane +  32] = a1;
    sh[wid][lane +  64] = a2;
    sh[wid][lane +  96] = a3;
    sh[wid][lane + 128] = a4;
    __syncwarp();

    int g = lane >> 2, j = lane & 3;
    const float4* q = &sh[wid][g * 20 + j];
    float4 w0 = q[0], w1 = q[4], w2 = q[8], w3 = q[12], w4 = q[16];

    // Per-lane max of 20 floats (FMNMX tree).
    float m01 = fmaxf(fmaxf(w0.x, w0.y), fmaxf(w0.z, w0.w));
    float m11 = fmaxf(fmaxf(w1.x, w1.y), fmaxf(w1.z, w1.w));
    float m21 = fmaxf(fmaxf(w2.x, w2.y), fmaxf(w2.z, w2.w));
    float m31 = fmaxf(fmaxf(w3.x, w3.y), fmaxf(w3.z, w3.w));
    float m41 = fmaxf(fmaxf(w4.x, w4.y), fmaxf(w4.z, w4.w));
    float m = fmaxf(fmaxf(fmaxf(m01, m11), fmaxf(m21, m31)), m41);

    // Order-preserving transform.
    unsigned t  = __float_as_uint(m);
    unsigned u0 = t ^ ((unsigned)((int)t >> 31) | 0x80000000u);

    // Group-of-4 max (xor 1, 2 stay within aligned quads).
    unsigned u = u0;
    u = max(u, __shfl_xor_sync(0xffffffffu, u, 1));
    u = max(u, __shfl_xor_sync(0xffffffffu, u, 2));

    // Winner lane within group (lowest j among maxima).
    unsigned ball = __ballot_sync(0xffffffffu, u0 == u);
    int wj = __ffs((ball >> (g * 4)) & 0xFu) - 1;

    // Per-lane local argmax class: reverse-overwrite scan -> first match wins.
    // class of element e of local chunk i = 4*j + 16*i + e.
    int cls = 0;
    {
        int cb = 4 * j;
        if (w4.w == m) cls = cb + 64 + 3;
        if (w4.z == m) cls = cb + 64 + 2;
        if (w4.y == m) cls = cb + 64 + 1;
        if (w4.x == m) cls = cb + 64;
        if (w3.w == m) cls = cb + 48 + 3;
        if (w3.z == m) cls = cb + 48 + 2;
        if (w3.y == m) cls = cb + 48 + 1;
        if (w3.x == m) cls = cb + 48;
        if (w2.w == m) cls = cb + 32 + 3;
        if (w2.z == m) cls = cb + 32 + 2;
        if (w2.y == m) cls = cb + 32 + 1;
        if (w2.x == m) cls = cb + 32;
        if (w1.w == m) cls = cb + 16 + 3;
        if (w1.z == m) cls = cb + 16 + 2;
        if (w1.y == m) cls = cb + 16 + 1;
        if (w1.x == m) cls = cb + 16;
        if (w0.w == m) cls = cb + 3;
        if (w0.z == m) cls = cb + 2;
        if (w0.y == m) cls = cb + 1;
        if (w0.x == m) cls = cb;
    }
    int label = __shfl_sync(0xffffffffu, cls, g * 4 + wj);

    if (j == 0) {                          // lanes 0,4,..,28 -> coalesced STG.64
        int qq = q0 + g;
        g_keys[b * NQ + qq] = ((unsigned long long)u << 32)
                            | ((unsigned)(1023 - qq) << 8) | (unsigned)label;
    }
}

// ---------------------------------------------------------------------------
// Bitonic helpers (descending).
// ---------------------------------------------------------------------------
__device__ __forceinline__ void shfl_merge(unsigned long long& v, unsigned i,
                                           unsigned k) {
    #pragma unroll
    for (int j = 16; j >= 1; j >>= 1) {
        unsigned long long pv = __shfl_xor_sync(0xffffffffu, v, j);
        bool keep_max = (((i & k) == 0) == ((i & (unsigned)j) == 0));
        v = keep_max ? (v > pv ? v : pv) : (v < pv ? v : pv);
    }
}
__device__ __forceinline__ void shfl_sort32(unsigned long long& v, unsigned i) {
    #pragma unroll
    for (unsigned k = 2; k <= 32; k <<= 1) {
        #pragma unroll
        for (int j = 16; j >= 1; j >>= 1) {
            if ((unsigned)j < k) {
                unsigned long long pv = __shfl_xor_sync(0xffffffffu, v, j);
                bool keep_max = (((i & k) == 0) == ((i & (unsigned)j) == 0));
                v = keep_max ? (v > pv ? v : pv) : (v < pv ? v : pv);
            }
        }
    }
}

// ---------------------------------------------------------------------------
// Merge-path rank select (descending, keys globally unique via query id).
// ---------------------------------------------------------------------------
__device__ __forceinline__ unsigned long long
rank_select(const unsigned long long* __restrict__ A,
            const unsigned long long* __restrict__ B,
            int r, int NA, int NBL) {
    int lo = r + 1 - NBL; if (lo < 0) lo = 0;
    int hi = r + 1;       if (hi > NA) hi = NA;
    while (lo < hi) {
        int i = (lo + hi) >> 1;
        if (B[r - i] > A[i]) hi = i; else lo = i + 1;
    }
    int is = lo, js = r + 1 - lo;
    unsigned long long ka = is ? A[is - 1] : 0xFFFFFFFFFFFFFFFFull;
    unsigned long long kb = js ? B[js - 1] : 0xFFFFFFFFFFFFFFFFull;
    return ka < kb ? ka : kb;
}

// ---------------------------------------------------------------------------
// Kernel 2 (fused): one block per batch row. Sort 4 chunks of 256 in lockstep
// (128 virtual threads per chunk), then two-phase merge-path top-300 +
// epilogue. grid = NB, block = 512.
// ---------------------------------------------------------------------------
__global__ void __launch_bounds__(512) topk_kernel(const float* __restrict__ boxes,
                                                   const float* __restrict__ tsz,
                                                   float* __restrict__ out) {
    __shared__ unsigned long long s[4 * CHUNK];
    __shared__ unsigned long long M[2][TOPK];
    int b    = blockIdx.x;
    int tid  = threadIdx.x;
    int c    = tid >> 7;        // chunk 0..3 (warps don't straddle chunks)
    int t128 = tid & 127;

    unsigned i0 = (unsigned)t128, i1 = (unsigned)t128 + 128;
    int e0 = c * CHUNK + (int)i0, e1 = c * CHUNK + (int)i1;
    unsigned long long v0 = (e0 < NQ) ? g_keys[b * NQ + e0] : 0ull;
    unsigned long long v1 = (e1 < NQ) ? g_keys[b * NQ + e1] : 0ull;

    shfl_sort32(v0, i0);
    shfl_sort32(v1, i1);
    s[c * CHUNK + i0] = v0;
    s[c * CHUNK + i1] = v1;
    __syncthreads();

    #pragma unroll
    for (unsigned k = 64; k <= CHUNK; k <<= 1) {
        for (unsigned j = k >> 1; j >= 32; j >>= 1) {
            #pragma unroll
            for (int half = 0; half < 2; half++) {
                unsigned idx = (unsigned)t128 + half * 128;
                unsigned ixj = idx ^ j;
                if (ixj > idx) {
                    unsigned long long a  = s[c * CHUNK + idx];
                    unsigned long long cc = s[c * CHUNK + ixj];
                    bool doswap = ((idx & k) == 0) ? (a < cc) : (a > cc);
                    if (doswap) { s[c * CHUNK + idx] = cc; s[c * CHUNK + ixj] = a; }
                }
            }
            __syncthreads();
        }
        v0 = s[c * CHUNK + i0]; v1 = s[c * CHUNK + i1];
        shfl_merge(v0, i0, k);
        shfl_merge(v1, i1, k);
        s[c * CHUNK + i0] = v0; s[c * CHUNK + i1] = v1;
        __syncthreads();
    }

    // Phase 1: top-300 of (chunk0 U chunk1) and (chunk2 U chunk3).
    for (int t = tid; t < 2 * TOPK; t += 512) {
        int pair = t / TOPK;
        int r    = t - pair * TOPK;
        const unsigned long long* A = s + pair * 2 * CHUNK;
        M[pair][r] = rank_select(A, A + CHUNK, r, CHUNK, CHUNK);
    }
    __syncthreads();

    // Phase 2: rank r of M[0] U M[1], then epilogue.
    if (tid < TOPK) {
        int r = tid;
        unsigned long long key = rank_select(M[0], M[1], r, TOPK, TOPK);

        unsigned u = (unsigned)(key >> 32);
        float logit = (u & 0x80000000u) ? __uint_as_float(u ^ 0x80000000u)
                                        : __uint_as_float(~u);
        float score = 1.0f / (1.0f + expf(-logit));
        bool  valid = (score > 0.05f);

        unsigned lw = (unsigned)(key & 0xffffffffu);
        int qi    = 1023 - (int)((lw >> 8) & 0x3ffu);
        int label = (int)(lw & 0xffu);

        float4 bx = ((const float4*)boxes)[b * NQ + qi];
        float img_h = tsz[b * 2 + 0];
        float img_w = tsz[b * 2 + 1];
        float x0 = (bx.x - 0.5f * bx.z) * img_w;
        float y0 = (bx.y - 0.5f * bx.w) * img_h;
        float x1 = (bx.x + 0.5f * bx.z) * img_w;
        float y1 = (bx.y + 0.5f * bx.w) * img_h;

        float* out_scores = out;
        float* out_labels = out + NB * TOPK;
        float* out_boxes  = out + 2 * NB * TOPK;

        out_scores[b * TOPK + r] = valid ? score : 0.0f;
        out_labels[b * TOPK + r] = valid ? (float)label : -1.0f;
        float4 ob = valid ? make_float4(x0, y0, x1, y1)
                          : make_float4(0.f, 0.f, 0.f, 0.f);
        ((float4*)out_boxes)[b * TOPK + r] = ob;
    }
}

// ---------------------------------------------------------------------------
extern "C" void kernel_launch(void* const* d_in, const int* in_sizes, int n_in,
                              void* d_out, int out_size) {
    const float* logits = (const float*)d_in[0];
    const float* boxes  = (const float*)d_in[1];
    const float* tsz    = (const float*)d_in[2];
    float* out = (float*)d_out;

    dim3 sgrid(16, NB);                    // 16 blocks x 64 queries = 1024 >= 1000
    score_kernel<<<sgrid, 256>>>(logits);
    topk_kernel<<<NB, 512>>>(boxes, tsz, out);
}